// round 1
// baseline (speedup 1.0000x reference)
#include <cuda_runtime.h>
#include <cstddef>

#define K27     27
#define N_DOWN  40000
#define N_UP    160000
#define C_DOWN  128
#define C_SKIP  64
#define C_CAT   192   // C_DOWN + C_SKIP
#define C_OUT   96

// Scratch: up-sampled feature map (pre-ReLU accumulator), 160000 x 128 f32 = 81.92 MB
__device__ float g_up[(size_t)N_UP * C_DOWN];

// ---------------------------------------------------------------------------
// PTX helpers
// ---------------------------------------------------------------------------

__device__ __forceinline__ void red_add_v4(float* p, float4 v) {
    asm volatile("red.global.add.v4.f32 [%0], {%1, %2, %3, %4};"
                 :: "l"(p), "f"(v.x), "f"(v.y), "f"(v.z), "f"(v.w)
                 : "memory");
}

__device__ __forceinline__ unsigned long long ffma2(unsigned long long a,
                                                    unsigned long long b,
                                                    unsigned long long c) {
    unsigned long long d;
    asm("fma.rn.f32x2 %0, %1, %2, %3;" : "=l"(d) : "l"(a), "l"(b), "l"(c));
    return d;
}

__device__ __forceinline__ unsigned long long pack2_dup(float x) {
    unsigned long long r;
    asm("mov.b64 %0, {%1, %1};" : "=l"(r) : "f"(x));
    return r;
}

__device__ __forceinline__ unsigned long long pack2(float x, float y) {
    unsigned long long r;
    asm("mov.b64 %0, {%1, %2};" : "=l"(r) : "f"(x), "f"(y));
    return r;
}

__device__ __forceinline__ void unpack2(unsigned long long v, float& x, float& y) {
    asm("mov.b64 {%0, %1}, %2;" : "=f"(x), "=f"(y) : "l"(v));
}

// ---------------------------------------------------------------------------
// Zero g_up and d_out
// ---------------------------------------------------------------------------
#define UP_F4   ((N_UP * C_DOWN) / 4)      // 5,120,000
#define OUT_F4  ((N_UP * C_OUT) / 4)       // 3,840,000
#define ZERO_F4 (UP_F4 + OUT_F4)           // 8,960,000

__global__ void __launch_bounds__(256) zero_kernel(float4* __restrict__ out4) {
    int i = blockIdx.x * 256 + threadIdx.x;   // grid sized exactly
    float4 z = make_float4(0.f, 0.f, 0.f, 0.f);
    if (i < UP_F4) {
        reinterpret_cast<float4*>(g_up)[i] = z;
    } else {
        out4[i - UP_F4] = z;
    }
}

// ---------------------------------------------------------------------------
// Deconv: for k in 27: g_up[out_idx[k][e]] += down[in_idx[k][e]] @ Wd[k]
// 1 warp handles 4 edges; each lane owns 4 output channels (lane*4..+3).
// Block = 256 threads (8 warps) -> 32 edges. grid = (1250, 27).
// ---------------------------------------------------------------------------
__global__ void __launch_bounds__(256) deconv_kernel(
    const float* __restrict__ down, const float* __restrict__ Wd,
    const int* __restrict__ iin, const int* __restrict__ iout)
{
    const int k    = blockIdx.y;
    const int warp = threadIdx.x >> 5;
    const int lane = threadIdx.x & 31;
    const int e0   = (blockIdx.x * 8 + warp) * 4;

    __shared__ float xs[8][4][C_DOWN];

    const float* W   = Wd + (size_t)k * C_DOWN * C_DOWN;
    const int* pin   = iin  + (size_t)k * N_DOWN;
    const int* pout  = iout + (size_t)k * N_DOWN;

    int oidx[4];
#pragma unroll
    for (int e = 0; e < 4; e++) {
        int src = pin[e0 + e];
        oidx[e] = pout[e0 + e];
        float4 v = reinterpret_cast<const float4*>(down + (size_t)src * C_DOWN)[lane];
        reinterpret_cast<float4*>(xs[warp][e])[lane] = v;
    }
    __syncwarp();

    unsigned long long acc[4][2] = {};
#pragma unroll 4
    for (int c = 0; c < C_DOWN; c++) {
        float4 w = __ldg(reinterpret_cast<const float4*>(W + (size_t)c * C_DOWN) + lane);
        unsigned long long w01 = pack2(w.x, w.y);
        unsigned long long w23 = pack2(w.z, w.w);
#pragma unroll
        for (int e = 0; e < 4; e++) {
            unsigned long long xx = pack2_dup(xs[warp][e][c]);
            acc[e][0] = ffma2(w01, xx, acc[e][0]);
            acc[e][1] = ffma2(w23, xx, acc[e][1]);
        }
    }

#pragma unroll
    for (int e = 0; e < 4; e++) {
        float4 r;
        unpack2(acc[e][0], r.x, r.y);
        unpack2(acc[e][1], r.z, r.w);
        red_add_v4(g_up + (size_t)oidx[e] * C_DOWN + lane * 4, r);
    }
}

// ---------------------------------------------------------------------------
// Conv: for k in 27: out[out_idx[k][e]] += relu_cat(in_idx[k][e]) @ Wc[k]
// where relu_cat(i) = [relu(g_up[i]) (128) | skip[i] (64)]  (192 ch, fused)
// Block = (24, 8) = 192 threads; 16 edges per block; each thread owns
// 4 output channels (tx*4..+3) of edges ey and ey+8. grid = (10000, 27).
// ---------------------------------------------------------------------------
#define CONV_EPB 16

__global__ void __launch_bounds__(192) conv_kernel(
    const float* __restrict__ skip, const float* __restrict__ Wc,
    const int* __restrict__ iin, const int* __restrict__ iout,
    float* __restrict__ out)
{
    const int k     = blockIdx.y;
    const int ebase = blockIdx.x * CONV_EPB;
    const int tid   = threadIdx.y * 24 + threadIdx.x;   // 0..191

    __shared__ float xs[CONV_EPB][C_CAT];
    __shared__ int   s_oidx[CONV_EPB];

    const int* pin  = iin  + (size_t)k * N_UP;
    const int* pout = iout + (size_t)k * N_UP;

    if (tid < CONV_EPB) s_oidx[tid] = pout[ebase + tid];

    // Gather: 16 edges * 48 float4 (32 up-f4 + 16 skip-f4) = 768 f4, 4/thread
#pragma unroll
    for (int t = 0; t < 4; t++) {
        int f    = tid + t * 192;      // 0..767
        int e    = f / 48;
        int comp = f % 48;
        int src  = pin[ebase + e];
        float4 v;
        if (comp < 32) {
            v = reinterpret_cast<const float4*>(g_up + (size_t)src * C_DOWN)[comp];
            v.x = fmaxf(v.x, 0.f); v.y = fmaxf(v.y, 0.f);
            v.z = fmaxf(v.z, 0.f); v.w = fmaxf(v.w, 0.f);
        } else {
            v = reinterpret_cast<const float4*>(skip + (size_t)src * C_SKIP)[comp - 32];
        }
        reinterpret_cast<float4*>(xs[e])[comp] = v;
    }
    __syncthreads();

    const float* W = Wc + (size_t)k * C_CAT * C_OUT;
    const int tx   = threadIdx.x;       // 0..23 -> channels tx*4..+3
    const int ey   = threadIdx.y;       // edges ey and ey+8

    unsigned long long a0[2] = {}, a1[2] = {};
#pragma unroll 4
    for (int c = 0; c < C_CAT; c++) {
        float4 w = __ldg(reinterpret_cast<const float4*>(W + (size_t)c * C_OUT) + tx);
        unsigned long long w01 = pack2(w.x, w.y);
        unsigned long long w23 = pack2(w.z, w.w);
        unsigned long long x0  = pack2_dup(xs[ey][c]);
        unsigned long long x1  = pack2_dup(xs[ey + 8][c]);
        a0[0] = ffma2(w01, x0, a0[0]);
        a0[1] = ffma2(w23, x0, a0[1]);
        a1[0] = ffma2(w01, x1, a1[0]);
        a1[1] = ffma2(w23, x1, a1[1]);
    }

    float4 r0, r1;
    unpack2(a0[0], r0.x, r0.y); unpack2(a0[1], r0.z, r0.w);
    unpack2(a1[0], r1.x, r1.y); unpack2(a1[1], r1.z, r1.w);
    red_add_v4(out + (size_t)s_oidx[ey]     * C_OUT + tx * 4, r0);
    red_add_v4(out + (size_t)s_oidx[ey + 8] * C_OUT + tx * 4, r1);
}

// ---------------------------------------------------------------------------
// Final ReLU over out
// ---------------------------------------------------------------------------
__global__ void __launch_bounds__(256) relu_kernel(float4* __restrict__ out4) {
    int i = blockIdx.x * 256 + threadIdx.x;  // grid sized exactly = OUT_F4
    float4 v = out4[i];
    v.x = fmaxf(v.x, 0.f); v.y = fmaxf(v.y, 0.f);
    v.z = fmaxf(v.z, 0.f); v.w = fmaxf(v.w, 0.f);
    out4[i] = v;
}

// ---------------------------------------------------------------------------
// Launch
// ---------------------------------------------------------------------------
extern "C" void kernel_launch(void* const* d_in, const int* in_sizes, int n_in,
                              void* d_out, int out_size)
{
    // Resolve inputs by element count (robust to ordering); same-size pairs
    // keep their relative order: (in_idx, out_idx).
    const float* skip   = nullptr;  // 160000*64   = 10,240,000
    const float* down   = nullptr;  // 40000*128   =  5,120,000
    const float* Wd     = nullptr;  // 27*128*128  =    442,368
    const float* Wc     = nullptr;  // 27*192*96   =    497,664
    const int*   d_iin  = nullptr;  // 27*40000    =  1,080,000 (first)
    const int*   d_iout = nullptr;  //               (second)
    const int*   c_iin  = nullptr;  // 27*160000   =  4,320,000 (first)
    const int*   c_iout = nullptr;  //               (second)

    for (int i = 0; i < n_in; i++) {
        int sz = in_sizes[i];
        if      (sz == N_UP * C_SKIP)           skip = (const float*)d_in[i];
        else if (sz == N_DOWN * C_DOWN)         down = (const float*)d_in[i];
        else if (sz == K27 * C_DOWN * C_DOWN)   Wd   = (const float*)d_in[i];
        else if (sz == K27 * C_CAT * C_OUT)     Wc   = (const float*)d_in[i];
        else if (sz == K27 * N_DOWN) {
            if (!d_iin) d_iin = (const int*)d_in[i]; else d_iout = (const int*)d_in[i];
        }
        else if (sz == K27 * N_UP) {
            if (!c_iin) c_iin = (const int*)d_in[i]; else c_iout = (const int*)d_in[i];
        }
    }

    float* out = (float*)d_out;

    zero_kernel<<<ZERO_F4 / 256, 256>>>((float4*)out);
    deconv_kernel<<<dim3(N_DOWN / 32, K27), 256>>>(down, Wd, d_iin, d_iout);
    conv_kernel<<<dim3(N_UP / CONV_EPB, K27), dim3(24, 8)>>>(skip, Wc, c_iin, c_iout, out);
    relu_kernel<<<OUT_F4 / 256, 256>>>((float4*)out);
}

// round 3
// speedup vs baseline: 3.2523x; 3.2523x over previous
#include <cuda_runtime.h>
#include <cstdint>
#include <cstddef>

#define K27     27
#define N_DOWN  40000
#define N_UP    160000
#define C_DOWN  128
#define C_SKIP  64
#define C_CAT   192
#define C_OUT   96

// Scratch globals (no cudaMalloc allowed)
__device__ float g_up [(size_t)N_UP * C_DOWN];            // 81.92 MB
__device__ float g_WdT[(size_t)K27 * C_DOWN * C_DOWN];    // W_deconv[k]^T  [k][n][c], tf32-rounded
__device__ float g_WcT[(size_t)K27 * C_OUT  * C_CAT];     // W_conv[k]^T    [k][n][c], tf32-rounded

// ---------------------------------------------------------------------------
// Helpers
// ---------------------------------------------------------------------------
__device__ __forceinline__ float to_tf32(float x) {
    float r;
    asm("cvt.rn.tf32.f32 %0, %1;" : "=f"(r) : "f"(x));
    return r;
}
__device__ __forceinline__ void red_add_v4(float* p, float4 v) {
    asm volatile("red.global.add.v4.f32 [%0], {%1, %2, %3, %4};"
                 :: "l"(p), "f"(v.x), "f"(v.y), "f"(v.z), "f"(v.w) : "memory");
}
// D(16x8) += A(16x8,tf32) * B(8x8,tf32);  A row-major frag, B col frag.
__device__ __forceinline__ void mma_tf32(float* c, const uint32_t* a,
                                         uint32_t b0, uint32_t b1) {
    asm("mma.sync.aligned.m16n8k8.row.col.f32.tf32.tf32.f32 "
        "{%0,%1,%2,%3}, {%4,%5,%6,%7}, {%8,%9}, {%0,%1,%2,%3};"
        : "+f"(c[0]), "+f"(c[1]), "+f"(c[2]), "+f"(c[3])
        : "r"(a[0]), "r"(a[1]), "r"(a[2]), "r"(a[3]), "r"(b0), "r"(b1));
}

// ---------------------------------------------------------------------------
// Zero g_up and d_out
// ---------------------------------------------------------------------------
#define UP_F4   ((N_UP * C_DOWN) / 4)
#define OUT_F4  ((N_UP * C_OUT) / 4)
#define ZERO_F4 (UP_F4 + OUT_F4)

__global__ void __launch_bounds__(256) zero_kernel(float4* __restrict__ out4) {
    int i = blockIdx.x * 256 + threadIdx.x;
    float4 z = make_float4(0.f, 0.f, 0.f, 0.f);
    if (i < UP_F4) reinterpret_cast<float4*>(g_up)[i] = z;
    else           out4[i - UP_F4] = z;
}

// ---------------------------------------------------------------------------
// Weight transpose + tf32 rounding
// ---------------------------------------------------------------------------
#define WD_ELEMS (K27 * C_DOWN * C_DOWN)
#define WC_ELEMS (K27 * C_OUT * C_CAT)
__global__ void __launch_bounds__(256) transpose_w_kernel(
    const float* __restrict__ Wd, const float* __restrict__ Wc)
{
    int i = blockIdx.x * 256 + threadIdx.x;
    if (i < WD_ELEMS) {
        int k = i / (C_DOWN * C_DOWN), r = i % (C_DOWN * C_DOWN);
        int n = r / C_DOWN, c = r % C_DOWN;
        g_WdT[i] = to_tf32(Wd[((size_t)k * C_DOWN + c) * C_DOWN + n]);
    } else {
        int j = i - WD_ELEMS;
        int k = j / (C_OUT * C_CAT), r = j % (C_OUT * C_CAT);
        int n = r / C_CAT, c = r % C_CAT;
        g_WcT[j] = to_tf32(Wc[((size_t)k * C_CAT + c) * C_OUT + n]);
    }
}

// ---------------------------------------------------------------------------
// Deconv MMA: tile of 128 edges: D[128,128] = A[128,128] @ WdT[k]^T, scatter.
// Row strides padded to 132 floats (132 % 32 == 4 -> conflict-free frags).
// 8 warps: 4 (M=32 each) x 2 (N=64 each). grid = (313, 27), 256 threads.
// ---------------------------------------------------------------------------
#define D_KP 132
#define D_A_F 0
#define D_B_F (128 * D_KP)                 // 16896 floats
#define D_OIDX_F (2 * 128 * D_KP)         // 33792 floats
#define D_SMEM ((2 * 128 * D_KP) * 4 + 512)

__global__ void __launch_bounds__(256, 1)
deconv_mma_kernel(const float* __restrict__ down,
                  const int* __restrict__ iin, const int* __restrict__ iout)
{
    extern __shared__ __align__(16) float sm[];
    float* As = sm + D_A_F;
    float* Bs = sm + D_B_F;
    int*   oidx = (int*)(sm + D_OIDX_F);

    const int tid = threadIdx.x, wid = tid >> 5, lane = tid & 31;
    const int g = lane >> 2, t4 = lane & 3;
    const int k = blockIdx.y;
    const int ebase = blockIdx.x * 128;
    const int nvalid = min(128, N_DOWN - ebase);

    const int* pin  = iin  + (size_t)k * N_DOWN + ebase;
    const int* pout = iout + (size_t)k * N_DOWN + ebase;
    if (tid < 128) oidx[tid] = (tid < nvalid) ? pout[tid] : -1;

    // Gather A: 2 threads/edge, 16 f4 each (row of 128 tf32)
    {
        int e  = tid >> 1;
        int cb = (tid & 1) * 16;
        if (e < nvalid) {
            const float4* src = (const float4*)(down + (size_t)pin[e] * C_DOWN);
#pragma unroll
            for (int j = 0; j < 16; j++) {
                float4 v = src[cb + j];
                v.x = to_tf32(v.x); v.y = to_tf32(v.y);
                v.z = to_tf32(v.z); v.w = to_tf32(v.w);
                *(float4*)&As[e * D_KP + (cb + j) * 4] = v;
            }
        } else {
            float4 z = make_float4(0.f, 0.f, 0.f, 0.f);
#pragma unroll
            for (int j = 0; j < 16; j++)
                *(float4*)&As[e * D_KP + (cb + j) * 4] = z;
        }
    }
    // Stage B: WdT[k] 128x128 -> padded rows. 4096 f4, 16/thread.
    {
        const float4* w4 = (const float4*)(g_WdT + (size_t)k * C_DOWN * C_DOWN);
#pragma unroll
        for (int j = 0; j < 16; j++) {
            int f = tid + j * 256;
            *(float4*)&Bs[(f >> 5) * D_KP + (f & 31) * 4] = w4[f];
        }
    }
    __syncthreads();

    const int mbase = (wid & 3) * 32;
    const int nbase = (wid >> 2) * 64;
    const uint32_t* Ap = (const uint32_t*)As + (mbase + g) * D_KP + t4;
    const uint32_t* Bp = (const uint32_t*)Bs + (nbase + g) * D_KP + t4;

    float c[2][8][4] = {};
#pragma unroll 4
    for (int s = 0; s < 16; s++) {
        const int kk = s * 8;
        uint32_t a[2][4];
#pragma unroll
        for (int mt = 0; mt < 2; mt++) {
            const uint32_t* p = Ap + mt * 16 * D_KP + kk;
            a[mt][0] = p[0]; a[mt][1] = p[8 * D_KP];
            a[mt][2] = p[4]; a[mt][3] = p[8 * D_KP + 4];
        }
#pragma unroll
        for (int j = 0; j < 8; j++) {
            const uint32_t* q = Bp + j * 8 * D_KP + kk;
            uint32_t b0 = q[0], b1 = q[4];
            mma_tf32(c[0][j], a[0], b0, b1);
            mma_tf32(c[1][j], a[1], b0, b1);
        }
    }
    __syncthreads();

    // Stage D into smem (reuse As region): [128][128]
#pragma unroll
    for (int mt = 0; mt < 2; mt++) {
        int row = mbase + mt * 16 + g;
#pragma unroll
        for (int j = 0; j < 8; j++) {
            int col = nbase + j * 8 + 2 * t4;
            *(float2*)&sm[row * 128 + col]       = make_float2(c[mt][j][0], c[mt][j][1]);
            *(float2*)&sm[(row + 8) * 128 + col] = make_float2(c[mt][j][2], c[mt][j][3]);
        }
    }
    __syncthreads();

    // Scatter: 4096 f4, 16/thread
#pragma unroll
    for (int t = 0; t < 16; t++) {
        int f = tid + t * 256;
        int e = f >> 5, q = f & 31;
        int o = oidx[e];
        if (o >= 0) {
            float4 v = *(float4*)&sm[e * 128 + q * 4];
            red_add_v4(g_up + (size_t)o * C_DOWN + q * 4, v);
        }
    }
}

// ---------------------------------------------------------------------------
// Conv MMA: tile of 128 edges: D[128,96] = relu_cat[128,192] @ WcT[k]^T.
// Row strides padded to 196 floats (196 % 32 == 4). 8 warps: 4 x 2 (N=48).
// grid = (1250, 27), 256 threads.
// ---------------------------------------------------------------------------
#define C_KP 196
#define C_A_F 0
#define C_B_F (128 * C_KP)                         // 25088 floats
#define C_OIDX_F (128 * C_KP + 96 * C_KP)          // 43904 floats
#define C_SMEM ((128 * C_KP + 96 * C_KP) * 4 + 512)

__global__ void __launch_bounds__(256, 1)
conv_mma_kernel(const float* __restrict__ skip,
                const int* __restrict__ iin, const int* __restrict__ iout,
                float* __restrict__ out)
{
    extern __shared__ __align__(16) float sm[];
    float* As = sm + C_A_F;
    float* Bs = sm + C_B_F;
    int*   oidx = (int*)(sm + C_OIDX_F);

    const int tid = threadIdx.x, wid = tid >> 5, lane = tid & 31;
    const int g = lane >> 2, t4 = lane & 3;
    const int k = blockIdx.y;
    const int ebase = blockIdx.x * 128;

    const int* pin  = iin  + (size_t)k * N_UP + ebase;
    const int* pout = iout + (size_t)k * N_UP + ebase;
    if (tid < 128) oidx[tid] = pout[tid];

    // Gather A (fused relu+concat): 2 threads/edge, 24 f4 each.
    {
        int e  = tid >> 1;
        int hh = tid & 1;
        int src = pin[e];
        const float4* up4 = (const float4*)(g_up + (size_t)src * C_DOWN);
        const float4* sk4 = (const float4*)(skip + (size_t)src * C_SKIP);
#pragma unroll
        for (int j = 0; j < 24; j++) {
            int comp = hh * 24 + j;
            float4 v;
            if (comp < 32) {
                v = up4[comp];
                v.x = to_tf32(fmaxf(v.x, 0.f)); v.y = to_tf32(fmaxf(v.y, 0.f));
                v.z = to_tf32(fmaxf(v.z, 0.f)); v.w = to_tf32(fmaxf(v.w, 0.f));
            } else {
                v = sk4[comp - 32];
                v.x = to_tf32(v.x); v.y = to_tf32(v.y);
                v.z = to_tf32(v.z); v.w = to_tf32(v.w);
            }
            *(float4*)&As[e * C_KP + comp * 4] = v;
        }
    }
    // Stage B: WcT[k] 96x192 -> padded rows. 4608 f4, 18/thread.
    {
        const float4* w4 = (const float4*)(g_WcT + (size_t)k * C_OUT * C_CAT);
#pragma unroll
        for (int j = 0; j < 18; j++) {
            int f = tid + j * 256;
            *(float4*)&Bs[(f / 48) * C_KP + (f % 48) * 4] = w4[f];
        }
    }
    __syncthreads();

    const int mbase = (wid & 3) * 32;
    const int nbase = (wid >> 2) * 48;
    const uint32_t* Ap = (const uint32_t*)As + (mbase + g) * C_KP + t4;
    const uint32_t* Bp = (const uint32_t*)Bs + (nbase + g) * C_KP + t4;

    float c[2][6][4] = {};
#pragma unroll 4
    for (int s = 0; s < 24; s++) {
        const int kk = s * 8;
        uint32_t a[2][4];
#pragma unroll
        for (int mt = 0; mt < 2; mt++) {
            const uint32_t* p = Ap + mt * 16 * C_KP + kk;
            a[mt][0] = p[0]; a[mt][1] = p[8 * C_KP];
            a[mt][2] = p[4]; a[mt][3] = p[8 * C_KP + 4];
        }
#pragma unroll
        for (int j = 0; j < 6; j++) {
            const uint32_t* q = Bp + j * 8 * C_KP + kk;
            uint32_t b0 = q[0], b1 = q[4];
            mma_tf32(c[0][j], a[0], b0, b1);
            mma_tf32(c[1][j], a[1], b0, b1);
        }
    }
    __syncthreads();

    // Stage D into smem (reuse As region): [128][96]
#pragma unroll
    for (int mt = 0; mt < 2; mt++) {
        int row = mbase + mt * 16 + g;
#pragma unroll
        for (int j = 0; j < 6; j++) {
            int col = nbase + j * 8 + 2 * t4;
            *(float2*)&sm[row * 96 + col]       = make_float2(c[mt][j][0], c[mt][j][1]);
            *(float2*)&sm[(row + 8) * 96 + col] = make_float2(c[mt][j][2], c[mt][j][3]);
        }
    }
    __syncthreads();

    // Scatter: 3072 f4, 12/thread
#pragma unroll
    for (int t = 0; t < 12; t++) {
        int f = tid + t * 256;
        int e = f / 24, q = f % 24;
        float4 v = *(float4*)&sm[e * 96 + q * 4];
        red_add_v4(out + (size_t)oidx[e] * C_OUT + q * 4, v);
    }
}

// ---------------------------------------------------------------------------
// Final ReLU
// ---------------------------------------------------------------------------
__global__ void __launch_bounds__(256) relu_kernel(float4* __restrict__ out4) {
    int i = blockIdx.x * 256 + threadIdx.x;
    float4 v = out4[i];
    v.x = fmaxf(v.x, 0.f); v.y = fmaxf(v.y, 0.f);
    v.z = fmaxf(v.z, 0.f); v.w = fmaxf(v.w, 0.f);
    out4[i] = v;
}

// ---------------------------------------------------------------------------
// Launch
// ---------------------------------------------------------------------------
extern "C" void kernel_launch(void* const* d_in, const int* in_sizes, int n_in,
                              void* d_out, int out_size)
{
    const float* skip = nullptr; const float* down = nullptr;
    const float* Wd = nullptr;   const float* Wc = nullptr;
    const int *d_iin = nullptr, *d_iout = nullptr, *c_iin = nullptr, *c_iout = nullptr;

    for (int i = 0; i < n_in; i++) {
        int sz = in_sizes[i];
        if      (sz == N_UP * C_SKIP)         skip = (const float*)d_in[i];
        else if (sz == N_DOWN * C_DOWN)       down = (const float*)d_in[i];
        else if (sz == K27 * C_DOWN * C_DOWN) Wd   = (const float*)d_in[i];
        else if (sz == K27 * C_CAT * C_OUT)   Wc   = (const float*)d_in[i];
        else if (sz == K27 * N_DOWN) { if (!d_iin) d_iin = (const int*)d_in[i]; else d_iout = (const int*)d_in[i]; }
        else if (sz == K27 * N_UP)   { if (!c_iin) c_iin = (const int*)d_in[i]; else c_iout = (const int*)d_in[i]; }
    }
    float* out = (float*)d_out;

    cudaFuncSetAttribute(deconv_mma_kernel, cudaFuncAttributeMaxDynamicSharedMemorySize, D_SMEM);
    cudaFuncSetAttribute(conv_mma_kernel,   cudaFuncAttributeMaxDynamicSharedMemorySize, C_SMEM);

    zero_kernel<<<ZERO_F4 / 256, 256>>>((float4*)out);
    transpose_w_kernel<<<(WD_ELEMS + WC_ELEMS) / 256, 256>>>(Wd, Wc);
    deconv_mma_kernel<<<dim3((N_DOWN + 127) / 128, K27), 256, D_SMEM>>>(down, d_iin, d_iout);
    conv_mma_kernel<<<dim3(N_UP / 128, K27), 256, C_SMEM>>>(skip, c_iin, c_iout, out);
    relu_kernel<<<OUT_F4 / 256, 256>>>((float4*)out);
}